// round 16
// baseline (speedup 1.0000x reference)
#include <cuda_runtime.h>
#include <cuda_fp16.h>
#include <cstdint>

// Problem constants
#define Bc  2
#define Sc  4096
#define Dc  768
#define Hc  12
#define DHc 64
#define BHc (Bc*Hc)          // 24

// Projected Q/K/V in fp16, layout [b*H+h][s][dh]
__device__ __half g_q[(size_t)BHc*Sc*DHc];
__device__ __half g_k[(size_t)BHc*Sc*DHc];
__device__ __half g_v[(size_t)BHc*Sc*DHc];

// ---------------------------------------------------------------------------
// Warp-MMA / async-copy primitives (plain PTX, legal on compute_103)
// ---------------------------------------------------------------------------
__device__ __forceinline__ uint32_t smem_u32(const void* p) {
    uint32_t a;
    asm("{ .reg .u64 t; cvta.to.shared.u64 t, %1; cvt.u32.u64 %0, t; }"
        : "=r"(a) : "l"(p));
    return a;
}
__device__ __forceinline__ void ldx4(uint32_t* r, uint32_t a) {
    asm volatile("ldmatrix.sync.aligned.m8n8.x4.shared.b16 {%0,%1,%2,%3}, [%4];"
        : "=r"(r[0]), "=r"(r[1]), "=r"(r[2]), "=r"(r[3]) : "r"(a) : "memory");
}
__device__ __forceinline__ void ldx4t(uint32_t* r, uint32_t a) {
    asm volatile("ldmatrix.sync.aligned.m8n8.x4.trans.shared.b16 {%0,%1,%2,%3}, [%4];"
        : "=r"(r[0]), "=r"(r[1]), "=r"(r[2]), "=r"(r[3]) : "r"(a) : "memory");
}
// D += A * B  (m16n8k16, fp16 in, f32 accum)
__device__ __forceinline__ void mma16816(float* d, const uint32_t* a, const uint32_t* b) {
    asm volatile("mma.sync.aligned.m16n8k16.row.col.f32.f16.f16.f32 "
        "{%0,%1,%2,%3}, {%4,%5,%6,%7}, {%8,%9}, {%0,%1,%2,%3};"
        : "+f"(d[0]), "+f"(d[1]), "+f"(d[2]), "+f"(d[3])
        : "r"(a[0]), "r"(a[1]), "r"(a[2]), "r"(a[3]), "r"(b[0]), "r"(b[1]));
}
__device__ __forceinline__ void cp16(uint32_t dst, const void* src) {
    asm volatile("cp.async.cg.shared.global [%0], [%1], 16;" :: "r"(dst), "l"(src));
}
#define CP_COMMIT() asm volatile("cp.async.commit_group;" ::: "memory")
#define CP_WAIT0()  asm volatile("cp.async.wait_group 0;"  ::: "memory")

__device__ __forceinline__ uint32_t pkh2(float a, float b) {
    __half2 t = __floats2half2_rn(a, b);    // a -> .x (low)
    return *reinterpret_cast<uint32_t*>(&t);
}

// MUFU exp2 (warp-wide MUFU: 32 lanes / 8 cyc / SMSP -> all softmax exps cost
// ~60us chip-wide on a pipe that overlaps with tensor; the old polynomial
// burned ~10 fma-pipe issue slots per element, which ncu showed as fma=25%).
__device__ __forceinline__ float ex2a(float x) {
    float r;
    asm("ex2.approx.ftz.f32 %0, %1;" : "=f"(r) : "f"(x));
    return r;
}
#define EXPC 0.18033688011112042f   // log2(e)/8 : exp(s/8) = 2^(s*EXPC)

// ===========================================================================
// Kernel 1: fused per-head QKV projection, fp16 mma.sync.
// grid (128, 12): bx = 64-row tile, by = head. One CTA computes Q,K,V for its
// head from ONE staging of the x tile (x L2 traffic /3 vs per-(which,head)).
// 4 warps (BM=64), launch_bounds(128,4) -> 4 CTAs/SM.
// ===========================================================================
#define QS 72
#define X_O 0
#define QW_O(i) (64*QS + (i)*64*QS)
#define QKV_BYTES ((64*QS * 4) * 2)        // 36864

__global__ void __launch_bounds__(128, 4) qkv_mma(
    const float* __restrict__ x, const float* __restrict__ Wq,
    const float* __restrict__ Wk, const float* __restrict__ Wv)
{
    extern __shared__ __half smq[];
    const uint32_t sb = smem_u32(smq);
    const int tid = threadIdx.x, w = tid >> 5, lane = tid & 31;
    const int grp = lane >> 2, tg = lane & 3;

    const int h = blockIdx.y;
    const float* Wp[3] = { Wq + (size_t)h * Dc * DHc,
                           Wk + (size_t)h * Dc * DHc,
                           Wv + (size_t)h * Dc * DHc };
    const int row0 = blockIdx.x * 64;

    float cf[3][8][4];
    #pragma unroll
    for (int q = 0; q < 3; q++)
        #pragma unroll
        for (int t = 0; t < 8; t++)
            #pragma unroll
            for (int e = 0; e < 4; e++) cf[q][t][e] = 0.f;

    const int arow  = 16 * w + (lane & 7) + 8 * ((lane >> 3) & 1);
    const int acol8 = 8 * (lane >> 4);
    const int bk    = (lane & 7) + 8 * ((lane >> 3) & 1);
    const int bn8   = 8 * (lane >> 4);

    for (int k0 = 0; k0 < Dc; k0 += 64) {
        __syncthreads();
        // stage x tile [64 x 64] fp32 -> fp16 (1024 float4 over 128 threads)
        #pragma unroll
        for (int it = 0; it < 8; it++) {
            int f = tid + it * 128;
            int r = f >> 4, c4 = f & 15;
            float4 v = *(const float4*)(x + (size_t)(row0 + r) * Dc + k0 + c4 * 4);
            *(uint2*)(smq + X_O + r * QS + c4 * 4) =
                make_uint2(pkh2(v.x, v.y), pkh2(v.z, v.w));
        }
        // stage Wq/Wk/Wv tiles [64 k x 64 n] fp32 -> fp16
        #pragma unroll
        for (int q = 0; q < 3; q++) {
            #pragma unroll
            for (int it = 0; it < 8; it++) {
                int f = tid + it * 128;
                int r = f >> 4, c4 = f & 15;
                float4 v = *(const float4*)(Wp[q] + (size_t)(k0 + r) * DHc + c4 * 4);
                *(uint2*)(smq + QW_O(q) + r * QS + c4 * 4) =
                    make_uint2(pkh2(v.x, v.y), pkh2(v.z, v.w));
            }
        }
        __syncthreads();

        #pragma unroll
        for (int kc = 0; kc < 4; kc++) {
            uint32_t ax[4];
            ldx4(ax, sb + (uint32_t)((X_O + arow * QS + 16 * kc + acol8) * 2));
            #pragma unroll
            for (int q = 0; q < 3; q++) {
                #pragma unroll
                for (int tp = 0; tp < 4; tp++) {
                    uint32_t wb[4];
                    ldx4t(wb, sb + (uint32_t)((QW_O(q) + (16 * kc + bk) * QS + 16 * tp + bn8) * 2));
                    mma16816(cf[q][2*tp],   ax, wb + 0);
                    mma16816(cf[q][2*tp+1], ax, wb + 2);
                }
            }
        }
    }

    // Epilogue: fp32 -> fp16, store all three outputs
    #pragma unroll
    for (int q = 0; q < 3; q++) {
        __half* Out = (q == 0 ? g_q : q == 1 ? g_k : g_v);
        #pragma unroll
        for (int t = 0; t < 8; t++) {
            int col = 8 * t + 2 * tg;
            #pragma unroll
            for (int half = 0; half < 2; half++) {
                int gr = row0 + 16 * w + grp + 8 * half;
                int b = gr >> 12, s = gr & (Sc - 1);
                size_t idx = ((size_t)(b * Hc + h) * Sc + s) * DHc + col;
                *(uint32_t*)(Out + idx) = pkh2(cf[q][t][2*half], cf[q][t][2*half + 1]);
            }
        }
    }
}

// ===========================================================================
// Kernel 2: causal flash attention, fp16 mma.sync, fixed-max softmax.
// R16 vs R15: polynomial exp replaced by MUFU ex2.approx (offloads the fma
// pipe; ~270 fewer issue slots per thread-tile). Everything else identical.
// grid (64, 24): bx -> q-tile (reversed, heavy first), by -> (b,h).
// ===========================================================================
#define FS  72
#define fQ  0
// buffers: [Q 64*FS][K0 64*FS][V0 64*FS][K1 64*FS][V1 64*FS]
#define FL_BYTES ((64*FS * 5) * 2)         // 46080

__device__ __forceinline__ void stage_kv(uint32_t sb, int buf,
    const __half* Kb, const __half* Vb, int k0, int tid)
{
    const uint32_t kOff = (uint32_t)((64*FS + buf * 2 * 64*FS) * 2);
    const uint32_t vOff = kOff + (uint32_t)(64*FS * 2);
    #pragma unroll
    for (int it = 0; it < 4; it++) {
        int id = tid + it * 128;
        int r = id >> 3, c = id & 7;
        uint32_t so = (uint32_t)((r * FS + c * 8) * 2);
        cp16(sb + kOff + so, Kb + (size_t)(k0 + r) * DHc + c * 8);
        cp16(sb + vOff + so, Vb + (size_t)(k0 + r) * DHc + c * 8);
    }
    CP_COMMIT();
}

__global__ void __launch_bounds__(128, 4) flash_mma(float* __restrict__ out)
{
    extern __shared__ __half smf[];
    const uint32_t sb = smem_u32(smf);
    const int tid = threadIdx.x, w = tid >> 5, lane = tid & 31;
    const int grp = lane >> 2, tg = lane & 3;

    const int bh = blockIdx.y;
    const int qt = gridDim.x - 1 - blockIdx.x;   // heavy tiles first
    const int q0 = qt * 64;

    const __half* Qb = g_q + (size_t)bh * Sc * DHc;
    const __half* Kb = g_k + (size_t)bh * Sc * DHc;
    const __half* Vb = g_v + (size_t)bh * Sc * DHc;

    // Stage Q (64 x 64 fp16) + first K/V tile via cp.async
    #pragma unroll
    for (int it = 0; it < 4; it++) {
        int id = tid + it * 128;
        int r = id >> 3, c = id & 7;
        cp16(sb + (uint32_t)((fQ + r * FS + c * 8) * 2),
             Qb + (size_t)(q0 + r) * DHc + c * 8);
    }
    CP_COMMIT();
    stage_kv(sb, 0, Kb, Vb, 0, tid);
    CP_WAIT0();
    __syncthreads();

    // Cache Q A-fragments for all 4 k-chunks (loop-invariant)
    const int arow  = 16 * w + (lane & 7) + 8 * ((lane >> 3) & 1);
    const int acol8 = 8 * (lane >> 4);
    uint32_t qf[4][4];
    #pragma unroll
    for (int kc = 0; kc < 4; kc++)
        ldx4(qf[kc], sb + (uint32_t)((fQ + arow * FS + 16 * kc + acol8) * 2));

    float of[8][4];
    #pragma unroll
    for (int t = 0; t < 8; t++)
        #pragma unroll
        for (int e = 0; e < 4; e++) of[t][e] = 0.f;
    float l0 = 0.f, l1 = 0.f;

    const int nkv   = qt + 1;
    const int row0g = q0 + 16 * w + grp;         // this thread's query row (half 0)
    const int lo8   = (lane & 7);
    const int hi16  = 8 * (lane >> 4);
    const int hi8   = 8 * ((lane >> 3) & 1);

    // Hoisted per-thread smem byte offsets (relative to K/V buffer base)
    const uint32_t kBaseOff = (uint32_t)(((hi16 + lo8) * FS + hi8) * 2);
    const uint32_t vBaseOff = (uint32_t)(((hi8 + lo8) * FS + hi16) * 2);

    for (int kt = 0; kt < nkv; kt++) {
        const int cur = kt & 1;
        const uint32_t kB = sb + (uint32_t)((64*FS + cur * 2 * 64*FS) * 2) + kBaseOff;
        const uint32_t vB = sb + (uint32_t)((64*FS + cur * 2 * 64*FS + 64*FS) * 2) + vBaseOff;
        const bool diag = (kt == nkv - 1);

        // Prefetch next tile into the other buffer (overlaps with compute)
        if (kt + 1 < nkv)
            stage_kv(sb, cur ^ 1, Kb, Vb, (kt + 1) * 64, tid);

        const int k0 = kt * 64;
        // Fused per-16-column chunk: S -> exp -> PV
        #pragma unroll
        for (int jt = 0; jt < 4; jt++) {
            float sf0[4] = {0.f, 0.f, 0.f, 0.f};
            float sf1[4] = {0.f, 0.f, 0.f, 0.f};
            #pragma unroll
            for (int kc = 0; kc < 4; kc++) {
                uint32_t kb[4];
                ldx4(kb, kB + (uint32_t)(jt * 16 * FS * 2 + kc * 32));
                mma16816(sf0, qf[kc], kb + 0);
                mma16816(sf1, qf[kc], kb + 2);
            }

            // softmax chunk: p = exp(s/8) = 2^(s*EXPC) via MUFU
            uint32_t pA[4];
            if (diag) {
                int jb0 = k0 + 16 * jt + 2 * tg;       // sf0 cols
                int jb1 = jb0 + 8;                     // sf1 cols
                float p00 = (jb0     <= row0g    ) ? ex2a(sf0[0] * EXPC) : 0.f;
                float p01 = (jb0 + 1 <= row0g    ) ? ex2a(sf0[1] * EXPC) : 0.f;
                float p02 = (jb0     <= row0g + 8) ? ex2a(sf0[2] * EXPC) : 0.f;
                float p03 = (jb0 + 1 <= row0g + 8) ? ex2a(sf0[3] * EXPC) : 0.f;
                float p10 = (jb1     <= row0g    ) ? ex2a(sf1[0] * EXPC) : 0.f;
                float p11 = (jb1 + 1 <= row0g    ) ? ex2a(sf1[1] * EXPC) : 0.f;
                float p12 = (jb1     <= row0g + 8) ? ex2a(sf1[2] * EXPC) : 0.f;
                float p13 = (jb1 + 1 <= row0g + 8) ? ex2a(sf1[3] * EXPC) : 0.f;
                pA[0] = pkh2(p00, p01); pA[1] = pkh2(p02, p03);
                pA[2] = pkh2(p10, p11); pA[3] = pkh2(p12, p13);
            } else {
                pA[0] = pkh2(ex2a(sf0[0] * EXPC), ex2a(sf0[1] * EXPC));
                pA[1] = pkh2(ex2a(sf0[2] * EXPC), ex2a(sf0[3] * EXPC));
                pA[2] = pkh2(ex2a(sf1[0] * EXPC), ex2a(sf1[1] * EXPC));
                pA[3] = pkh2(ex2a(sf1[2] * EXPC), ex2a(sf1[3] * EXPC));
            }
            // accumulate l from the rounded fp16 values (cancels P rounding)
            #pragma unroll
            for (int u = 0; u < 4; u++) {
                __half2 hv = *reinterpret_cast<__half2*>(&pA[u]);
                float s2 = __low2float(hv) + __high2float(hv);
                if (u == 0 || u == 2) l0 += s2; else l1 += s2;
            }

            // PV chunk: O += P[:,16jt..] V[16jt.., :]
            #pragma unroll
            for (int et = 0; et < 4; et++) {
                uint32_t vb[4];
                ldx4t(vb, vB + (uint32_t)(jt * 16 * FS * 2 + et * 32));
                mma16816(of[2*et],   pA, vb + 0);
                mma16816(of[2*et+1], pA, vb + 2);
            }
        }

        // Wait for the prefetched tile; barrier also releases this buffer
        // for the prefetch issued in the NEXT iteration.
        if (kt + 1 < nkv) {
            CP_WAIT0();
            __syncthreads();
        }
    }

    // Epilogue: quad-reduce l, divide, store
    l0 += __shfl_xor_sync(0xffffffffu, l0, 1);
    l0 += __shfl_xor_sync(0xffffffffu, l0, 2);
    l1 += __shfl_xor_sync(0xffffffffu, l1, 1);
    l1 += __shfl_xor_sync(0xffffffffu, l1, 2);
    const float inv0 = 1.0f / l0, inv1 = 1.0f / l1;
    const int b = bh / Hc, h = bh % Hc;
    const int r0 = row0g, r1 = row0g + 8;
    #pragma unroll
    for (int t = 0; t < 8; t++) {
        int col = 8 * t + 2 * tg;
        float2 v0 = make_float2(of[t][0] * inv0, of[t][1] * inv0);
        float2 v1 = make_float2(of[t][2] * inv1, of[t][3] * inv1);
        *(float2*)(out + ((size_t)b * Sc + r0) * (Hc * DHc) + h * DHc + col) = v0;
        *(float2*)(out + ((size_t)b * Sc + r1) * (Hc * DHc) + h * DHc + col) = v1;
    }
}

// ---------------------------------------------------------------------------
extern "C" void kernel_launch(void* const* d_in, const int* in_sizes, int n_in,
                              void* d_out, int out_size)
{
    const float* x  = (const float*)d_in[0];
    const float* Wq = (const float*)d_in[1];
    const float* Wk = (const float*)d_in[2];
    const float* Wv = (const float*)d_in[3];
    float* out = (float*)d_out;

    cudaFuncSetAttribute(qkv_mma,   cudaFuncAttributeMaxDynamicSharedMemorySize, QKV_BYTES);
    cudaFuncSetAttribute(flash_mma, cudaFuncAttributeMaxDynamicSharedMemorySize, FL_BYTES);

    qkv_mma<<<dim3(128, 12), 128, QKV_BYTES>>>(x, Wq, Wk, Wv);
    flash_mma<<<dim3(64, BHc), 128, FL_BYTES>>>(out);
}

// round 17
// speedup vs baseline: 1.6353x; 1.6353x over previous
#include <cuda_runtime.h>
#include <cuda_fp16.h>
#include <cstdint>

// Problem constants
#define Bc  2
#define Sc  4096
#define Dc  768
#define Hc  12
#define DHc 64
#define BHc (Bc*Hc)          // 24

// Projected Q/K/V in fp16, layout [b*H+h][s][dh]
__device__ __half g_q[(size_t)BHc*Sc*DHc];
__device__ __half g_k[(size_t)BHc*Sc*DHc];
__device__ __half g_v[(size_t)BHc*Sc*DHc];

// ---------------------------------------------------------------------------
// Warp-MMA / async-copy primitives (plain PTX, legal on compute_103)
// ---------------------------------------------------------------------------
__device__ __forceinline__ uint32_t smem_u32(const void* p) {
    uint32_t a;
    asm("{ .reg .u64 t; cvta.to.shared.u64 t, %1; cvt.u32.u64 %0, t; }"
        : "=r"(a) : "l"(p));
    return a;
}
__device__ __forceinline__ void ldx4(uint32_t* r, uint32_t a) {
    asm volatile("ldmatrix.sync.aligned.m8n8.x4.shared.b16 {%0,%1,%2,%3}, [%4];"
        : "=r"(r[0]), "=r"(r[1]), "=r"(r[2]), "=r"(r[3]) : "r"(a) : "memory");
}
__device__ __forceinline__ void ldx4t(uint32_t* r, uint32_t a) {
    asm volatile("ldmatrix.sync.aligned.m8n8.x4.trans.shared.b16 {%0,%1,%2,%3}, [%4];"
        : "=r"(r[0]), "=r"(r[1]), "=r"(r[2]), "=r"(r[3]) : "r"(a) : "memory");
}
// D += A * B  (m16n8k16, fp16 in, f32 accum)
__device__ __forceinline__ void mma16816(float* d, const uint32_t* a, const uint32_t* b) {
    asm volatile("mma.sync.aligned.m16n8k16.row.col.f32.f16.f16.f32 "
        "{%0,%1,%2,%3}, {%4,%5,%6,%7}, {%8,%9}, {%0,%1,%2,%3};"
        : "+f"(d[0]), "+f"(d[1]), "+f"(d[2]), "+f"(d[3])
        : "r"(a[0]), "r"(a[1]), "r"(a[2]), "r"(a[3]), "r"(b[0]), "r"(b[1]));
}
__device__ __forceinline__ void cp16(uint32_t dst, const void* src) {
    asm volatile("cp.async.cg.shared.global [%0], [%1], 16;" :: "r"(dst), "l"(src));
}
#define CP_COMMIT() asm volatile("cp.async.commit_group;" ::: "memory")
#define CP_WAIT0()  asm volatile("cp.async.wait_group 0;"  ::: "memory")

__device__ __forceinline__ uint32_t pkh2(float a, float b) {
    __half2 t = __floats2half2_rn(a, b);    // a -> .x (low)
    return *reinterpret_cast<uint32_t*>(&t);
}

// MUFU exp2: warp-wide MUFU = 32 lanes / 8 cyc / SMSP, overlaps with tensor
// pipe. (Validated R16: fma 25.3%->10.8%, flash 260->185us.)
__device__ __forceinline__ float ex2a(float x) {
    float r;
    asm("ex2.approx.ftz.f32 %0, %1;" : "=f"(r) : "f"(x));
    return r;
}
#define EXPC 0.18033688011112042f   // log2(e)/8 : exp(s/8) = 2^(s*EXPC)

// ===========================================================================
// Kernel 1: QKV projection, fp16 mma.sync — REVERTED to the R15 version
// (measured 154us; ~L2-bound). The R16 3-way fusion spilled (96 accum regs
// under a 128-reg cap) and ran ~368us.
// grid (64, 36): bx = 128-row tile, by = (which, head). (256,2).
// ===========================================================================
#define QS 72
#define X_O 0
#define W_O (128*QS)
#define QKV_BYTES ((128*QS + 64*QS) * 2)   // 27648

__global__ void __launch_bounds__(256, 2) qkv_mma(
    const float* __restrict__ x, const float* __restrict__ Wq,
    const float* __restrict__ Wk, const float* __restrict__ Wv)
{
    extern __shared__ __half smq[];
    const uint32_t sb = smem_u32(smq);
    const int tid = threadIdx.x, w = tid >> 5, lane = tid & 31;
    const int grp = lane >> 2, tg = lane & 3;

    const int wsel  = blockIdx.y;
    const int which = wsel / Hc;
    const int h     = wsel % Hc;
    const float* W  = (which == 0 ? Wq : which == 1 ? Wk : Wv) + (size_t)h * Dc * DHc;
    __half* Out     = (which == 0 ? g_q : which == 1 ? g_k : g_v);
    const int row0  = blockIdx.x * 128;

    float cf[8][4];
    #pragma unroll
    for (int t = 0; t < 8; t++)
        #pragma unroll
        for (int e = 0; e < 4; e++) cf[t][e] = 0.f;

    const int arow  = 16 * w + (lane & 7) + 8 * ((lane >> 3) & 1);
    const int acol8 = 8 * (lane >> 4);
    const int bk    = (lane & 7) + 8 * ((lane >> 3) & 1);
    const int bn8   = 8 * (lane >> 4);

    for (int k0 = 0; k0 < Dc; k0 += 64) {
        __syncthreads();
        #pragma unroll
        for (int it = 0; it < 8; it++) {
            int f = tid + it * 256;
            int r = f >> 4, c4 = f & 15;
            float4 v = *(const float4*)(x + (size_t)(row0 + r) * Dc + k0 + c4 * 4);
            *(uint2*)(smq + X_O + r * QS + c4 * 4) =
                make_uint2(pkh2(v.x, v.y), pkh2(v.z, v.w));
        }
        #pragma unroll
        for (int it = 0; it < 4; it++) {
            int f = tid + it * 256;
            int r = f >> 4, c4 = f & 15;
            float4 v = *(const float4*)(W + (size_t)(k0 + r) * DHc + c4 * 4);
            *(uint2*)(smq + W_O + r * QS + c4 * 4) =
                make_uint2(pkh2(v.x, v.y), pkh2(v.z, v.w));
        }
        __syncthreads();

        #pragma unroll
        for (int kc = 0; kc < 4; kc++) {
            uint32_t ax[4];
            ldx4(ax, sb + (uint32_t)((X_O + arow * QS + 16 * kc + acol8) * 2));
            #pragma unroll
            for (int tp = 0; tp < 4; tp++) {
                uint32_t wb[4];
                ldx4t(wb, sb + (uint32_t)((W_O + (16 * kc + bk) * QS + 16 * tp + bn8) * 2));
                mma16816(cf[2*tp],   ax, wb + 0);
                mma16816(cf[2*tp+1], ax, wb + 2);
            }
        }
    }

    #pragma unroll
    for (int t = 0; t < 8; t++) {
        int col = 8 * t + 2 * tg;
        #pragma unroll
        for (int half = 0; half < 2; half++) {
            int gr = row0 + 16 * w + grp + 8 * half;
            int b = gr >> 12, s = gr & (Sc - 1);
            size_t idx = ((size_t)(b * Hc + h) * Sc + s) * DHc + col;
            *(uint32_t*)(Out + idx) = pkh2(cf[t][2*half], cf[t][2*half + 1]);
        }
    }
}

// ===========================================================================
// Kernel 2: causal flash attention — KEPT byte-identical to R16 (185us,
// tensor 46.1%). fp16 mma.sync, fixed-max softmax, MUFU exp, double-buffered
// cp.async K/V, fused per-16-col S->exp->PV chunks, (128,4).
// grid (64, 24): bx -> q-tile (reversed, heavy first), by -> (b,h).
// ===========================================================================
#define FS  72
#define fQ  0
// buffers: [Q 64*FS][K0 64*FS][V0 64*FS][K1 64*FS][V1 64*FS]
#define FL_BYTES ((64*FS * 5) * 2)         // 46080

__device__ __forceinline__ void stage_kv(uint32_t sb, int buf,
    const __half* Kb, const __half* Vb, int k0, int tid)
{
    const uint32_t kOff = (uint32_t)((64*FS + buf * 2 * 64*FS) * 2);
    const uint32_t vOff = kOff + (uint32_t)(64*FS * 2);
    #pragma unroll
    for (int it = 0; it < 4; it++) {
        int id = tid + it * 128;
        int r = id >> 3, c = id & 7;
        uint32_t so = (uint32_t)((r * FS + c * 8) * 2);
        cp16(sb + kOff + so, Kb + (size_t)(k0 + r) * DHc + c * 8);
        cp16(sb + vOff + so, Vb + (size_t)(k0 + r) * DHc + c * 8);
    }
    CP_COMMIT();
}

__global__ void __launch_bounds__(128, 4) flash_mma(float* __restrict__ out)
{
    extern __shared__ __half smf[];
    const uint32_t sb = smem_u32(smf);
    const int tid = threadIdx.x, w = tid >> 5, lane = tid & 31;
    const int grp = lane >> 2, tg = lane & 3;

    const int bh = blockIdx.y;
    const int qt = gridDim.x - 1 - blockIdx.x;   // heavy tiles first
    const int q0 = qt * 64;

    const __half* Qb = g_q + (size_t)bh * Sc * DHc;
    const __half* Kb = g_k + (size_t)bh * Sc * DHc;
    const __half* Vb = g_v + (size_t)bh * Sc * DHc;

    // Stage Q (64 x 64 fp16) + first K/V tile via cp.async
    #pragma unroll
    for (int it = 0; it < 4; it++) {
        int id = tid + it * 128;
        int r = id >> 3, c = id & 7;
        cp16(sb + (uint32_t)((fQ + r * FS + c * 8) * 2),
             Qb + (size_t)(q0 + r) * DHc + c * 8);
    }
    CP_COMMIT();
    stage_kv(sb, 0, Kb, Vb, 0, tid);
    CP_WAIT0();
    __syncthreads();

    // Cache Q A-fragments for all 4 k-chunks (loop-invariant)
    const int arow  = 16 * w + (lane & 7) + 8 * ((lane >> 3) & 1);
    const int acol8 = 8 * (lane >> 4);
    uint32_t qf[4][4];
    #pragma unroll
    for (int kc = 0; kc < 4; kc++)
        ldx4(qf[kc], sb + (uint32_t)((fQ + arow * FS + 16 * kc + acol8) * 2));

    float of[8][4];
    #pragma unroll
    for (int t = 0; t < 8; t++)
        #pragma unroll
        for (int e = 0; e < 4; e++) of[t][e] = 0.f;
    float l0 = 0.f, l1 = 0.f;

    const int nkv   = qt + 1;
    const int row0g = q0 + 16 * w + grp;         // this thread's query row (half 0)
    const int lo8   = (lane & 7);
    const int hi16  = 8 * (lane >> 4);
    const int hi8   = 8 * ((lane >> 3) & 1);

    // Hoisted per-thread smem byte offsets (relative to K/V buffer base)
    const uint32_t kBaseOff = (uint32_t)(((hi16 + lo8) * FS + hi8) * 2);
    const uint32_t vBaseOff = (uint32_t)(((hi8 + lo8) * FS + hi16) * 2);

    for (int kt = 0; kt < nkv; kt++) {
        const int cur = kt & 1;
        const uint32_t kB = sb + (uint32_t)((64*FS + cur * 2 * 64*FS) * 2) + kBaseOff;
        const uint32_t vB = sb + (uint32_t)((64*FS + cur * 2 * 64*FS + 64*FS) * 2) + vBaseOff;
        const bool diag = (kt == nkv - 1);

        // Prefetch next tile into the other buffer (overlaps with compute)
        if (kt + 1 < nkv)
            stage_kv(sb, cur ^ 1, Kb, Vb, (kt + 1) * 64, tid);

        const int k0 = kt * 64;
        // Fused per-16-column chunk: S -> exp -> PV
        #pragma unroll
        for (int jt = 0; jt < 4; jt++) {
            float sf0[4] = {0.f, 0.f, 0.f, 0.f};
            float sf1[4] = {0.f, 0.f, 0.f, 0.f};
            #pragma unroll
            for (int kc = 0; kc < 4; kc++) {
                uint32_t kb[4];
                ldx4(kb, kB + (uint32_t)(jt * 16 * FS * 2 + kc * 32));
                mma16816(sf0, qf[kc], kb + 0);
                mma16816(sf1, qf[kc], kb + 2);
            }

            // softmax chunk: p = exp(s/8) = 2^(s*EXPC) via MUFU
            uint32_t pA[4];
            if (diag) {
                int jb0 = k0 + 16 * jt + 2 * tg;       // sf0 cols
                int jb1 = jb0 + 8;                     // sf1 cols
                float p00 = (jb0     <= row0g    ) ? ex2a(sf0[0] * EXPC) : 0.f;
                float p01 = (jb0 + 1 <= row0g    ) ? ex2a(sf0[1] * EXPC) : 0.f;
                float p02 = (jb0     <= row0g + 8) ? ex2a(sf0[2] * EXPC) : 0.f;
                float p03 = (jb0 + 1 <= row0g + 8) ? ex2a(sf0[3] * EXPC) : 0.f;
                float p10 = (jb1     <= row0g    ) ? ex2a(sf1[0] * EXPC) : 0.f;
                float p11 = (jb1 + 1 <= row0g    ) ? ex2a(sf1[1] * EXPC) : 0.f;
                float p12 = (jb1     <= row0g + 8) ? ex2a(sf1[2] * EXPC) : 0.f;
                float p13 = (jb1 + 1 <= row0g + 8) ? ex2a(sf1[3] * EXPC) : 0.f;
                pA[0] = pkh2(p00, p01); pA[1] = pkh2(p02, p03);
                pA[2] = pkh2(p10, p11); pA[3] = pkh2(p12, p13);
            } else {
                pA[0] = pkh2(ex2a(sf0[0] * EXPC), ex2a(sf0[1] * EXPC));
                pA[1] = pkh2(ex2a(sf0[2] * EXPC), ex2a(sf0[3] * EXPC));
                pA[2] = pkh2(ex2a(sf1[0] * EXPC), ex2a(sf1[1] * EXPC));
                pA[3] = pkh2(ex2a(sf1[2] * EXPC), ex2a(sf1[3] * EXPC));
            }
            // accumulate l from the rounded fp16 values (cancels P rounding)
            #pragma unroll
            for (int u = 0; u < 4; u++) {
                __half2 hv = *reinterpret_cast<__half2*>(&pA[u]);
                float s2 = __low2float(hv) + __high2float(hv);
                if (u == 0 || u == 2) l0 += s2; else l1 += s2;
            }

            // PV chunk: O += P[:,16jt..] V[16jt.., :]
            #pragma unroll
            for (int et = 0; et < 4; et++) {
                uint32_t vb[4];
                ldx4t(vb, vB + (uint32_t)(jt * 16 * FS * 2 + et * 32));
                mma16816(of[2*et],   pA, vb + 0);
                mma16816(of[2*et+1], pA, vb + 2);
            }
        }

        // Wait for the prefetched tile; barrier also releases this buffer
        // for the prefetch issued in the NEXT iteration.
        if (kt + 1 < nkv) {
            CP_WAIT0();
            __syncthreads();
        }
    }

    // Epilogue: quad-reduce l, divide, store
    l0 += __shfl_xor_sync(0xffffffffu, l0, 1);
    l0 += __shfl_xor_sync(0xffffffffu, l0, 2);
    l1 += __shfl_xor_sync(0xffffffffu, l1, 1);
    l1 += __shfl_xor_sync(0xffffffffu, l1, 2);
    const float inv0 = 1.0f / l0, inv1 = 1.0f / l1;
    const int b = bh / Hc, h = bh % Hc;
    const int r0 = row0g, r1 = row0g + 8;
    #pragma unroll
    for (int t = 0; t < 8; t++) {
        int col = 8 * t + 2 * tg;
        float2 v0 = make_float2(of[t][0] * inv0, of[t][1] * inv0);
        float2 v1 = make_float2(of[t][2] * inv1, of[t][3] * inv1);
        *(float2*)(out + ((size_t)b * Sc + r0) * (Hc * DHc) + h * DHc + col) = v0;
        *(float2*)(out + ((size_t)b * Sc + r1) * (Hc * DHc) + h * DHc + col) = v1;
    }
}

// ---------------------------------------------------------------------------
extern "C" void kernel_launch(void* const* d_in, const int* in_sizes, int n_in,
                              void* d_out, int out_size)
{
    const float* x  = (const float*)d_in[0];
    const float* Wq = (const float*)d_in[1];
    const float* Wk = (const float*)d_in[2];
    const float* Wv = (const float*)d_in[3];
    float* out = (float*)d_out;

    cudaFuncSetAttribute(qkv_mma,   cudaFuncAttributeMaxDynamicSharedMemorySize, QKV_BYTES);
    cudaFuncSetAttribute(flash_mma, cudaFuncAttributeMaxDynamicSharedMemorySize, FL_BYTES);

    qkv_mma<<<dim3(64, 36), 256, QKV_BYTES>>>(x, Wq, Wk, Wv);
    flash_mma<<<dim3(64, BHc), 128, FL_BYTES>>>(out);
}